// round 1
// baseline (speedup 1.0000x reference)
#include <cuda_runtime.h>
#include <cuda_bf16.h>

// Scratch buffers (N=50000 fixed by the problem). __device__ globals: allowed.
#define MAXN 50000
__device__ float g_sup[MAXN * 64];  // sup1, then a2 (pre-aggregated h1)
__device__ float g_a[MAXN * 64];    // a1/h1, then sup3 ([N,32])

// ---------------------------------------------------------------------------
// GEMM: out[n,M] = H[n,K] @ W[K,M]  (+ optional bias & sigmoid epilogue)
// 128 threads, TM=4 features/thread, TN nodes/thread. W + X tile in shared.
// ---------------------------------------------------------------------------
template <int K, int M, int TN, bool SIG>
__global__ __launch_bounds__(128) void gemm_kernel(
    const float* __restrict__ H, const float* __restrict__ Wm,
    const float* __restrict__ bias, float* __restrict__ out, int n) {
    constexpr int THREADS = 128;
    constexpr int TM = 4;
    constexpr int FG = M / TM;                 // threads per node-row
    constexpr int NPB = (THREADS / FG) * TN;   // nodes per block

    __shared__ float shW[K * M];
    __shared__ float shX[NPB][K + 1];

    int node0 = blockIdx.x * NPB;

    for (int i = threadIdx.x; i < K * M; i += THREADS) shW[i] = Wm[i];
    for (int i = threadIdx.x; i < NPB * K; i += THREADS) {
        int r = i / K, c = i - r * K;
        int node = node0 + r;
        shX[r][c] = (node < n) ? H[(size_t)node * K + c] : 0.0f;
    }
    __syncthreads();

    int group = threadIdx.x / FG;
    int f0 = (threadIdx.x % FG) * TM;

    float acc[TN][TM];
#pragma unroll
    for (int t = 0; t < TN; t++)
#pragma unroll
        for (int j = 0; j < TM; j++) acc[t][j] = 0.0f;

#pragma unroll
    for (int k = 0; k < K; k++) {
        float4 wv = *reinterpret_cast<const float4*>(&shW[k * M + f0]);
#pragma unroll
        for (int t = 0; t < TN; t++) {
            float xv = shX[group * TN + t][k];
            acc[t][0] += xv * wv.x;
            acc[t][1] += xv * wv.y;
            acc[t][2] += xv * wv.z;
            acc[t][3] += xv * wv.w;
        }
    }

#pragma unroll
    for (int t = 0; t < TN; t++) {
        int node = node0 + group * TN + t;
        if (node >= n) continue;
        float4 r;
        if (SIG) {
            float4 bv = *reinterpret_cast<const float4*>(&bias[f0]);
            r.x = 1.0f / (1.0f + __expf(-(acc[t][0] + bv.x)));
            r.y = 1.0f / (1.0f + __expf(-(acc[t][1] + bv.y)));
            r.z = 1.0f / (1.0f + __expf(-(acc[t][2] + bv.z)));
            r.w = 1.0f / (1.0f + __expf(-(acc[t][3] + bv.w)));
        } else {
            r.x = acc[t][0]; r.y = acc[t][1]; r.z = acc[t][2]; r.w = acc[t][3];
        }
        *reinterpret_cast<float4*>(&out[(size_t)node * M + f0]) = r;
    }
}

// ---------------------------------------------------------------------------
// Fill agg with per-row bias (or zeros if bias==nullptr). M power of two.
// ---------------------------------------------------------------------------
template <int M>
__global__ void fill_kernel(float* __restrict__ out, const float* __restrict__ bias,
                            int total) {
    int i = blockIdx.x * blockDim.x + threadIdx.x;
    if (i < total) out[i] = bias ? __ldg(&bias[i & (M - 1)]) : 0.0f;
}

// ---------------------------------------------------------------------------
// Edge scatter: agg[dst] += sup[src] * w   (one warp per edge)
// ---------------------------------------------------------------------------
template <int M>
__global__ __launch_bounds__(256) void scatter_kernel(
    const float* __restrict__ sup, const int* __restrict__ src,
    const int* __restrict__ dst, const float* __restrict__ ew,
    float* __restrict__ agg, int E) {
    int warp = (blockIdx.x * blockDim.x + threadIdx.x) >> 5;
    int lane = threadIdx.x & 31;
    if (warp >= E) return;
    int s = __ldg(&src[warp]);
    int d = __ldg(&dst[warp]);
    float w = __ldg(&ew[warp]);
    if (M == 64) {
        float2 v = *reinterpret_cast<const float2*>(&sup[(size_t)s * 64 + lane * 2]);
        atomicAdd(&agg[(size_t)d * 64 + lane * 2 + 0], v.x * w);
        atomicAdd(&agg[(size_t)d * 64 + lane * 2 + 1], v.y * w);
    } else {  // M == 32
        float v = __ldg(&sup[(size_t)s * 32 + lane]);
        atomicAdd(&agg[(size_t)d * 32 + lane], v * w);
    }
}

// ---------------------------------------------------------------------------
// Elementwise sigmoid in place
// ---------------------------------------------------------------------------
__global__ void sigmoid_kernel(float* __restrict__ a, int total) {
    int i = blockIdx.x * blockDim.x + threadIdx.x;
    if (i < total) a[i] = 1.0f / (1.0f + __expf(-a[i]));
}

extern "C" void kernel_launch(void* const* d_in, const int* in_sizes, int n_in,
                              void* d_out, int out_size) {
    const float* x  = (const float*)d_in[0];
    const int*   ei = (const int*)d_in[1];
    const float* ew = (const float*)d_in[2];
    const float* W1 = (const float*)d_in[3];
    const float* b1 = (const float*)d_in[4];
    const float* W2 = (const float*)d_in[5];
    const float* b2 = (const float*)d_in[6];
    const float* W3 = (const float*)d_in[7];
    const float* b3 = (const float*)d_in[8];

    int n = in_sizes[0] / 128;   // 50000
    int E = in_sizes[2];         // 500000
    const int* src = ei;
    const int* dst = ei + E;

    float* out  = (float*)d_out;              // [n, 32]
    float* feat = out + (size_t)n * 32;       // [n, 128]

    float *sup, *abuf;
    cudaGetSymbolAddress((void**)&sup, g_sup);
    cudaGetSymbolAddress((void**)&abuf, g_a);

    int scat_blocks = (E * 32 + 255) / 256;

    // ---- Layer 1: sup1 = x @ W1 ; a1 = b1 + agg(sup1) ; h1 = sigmoid(a1) ----
    {
        constexpr int NPB = (128 / (64 / 4)) * 2;  // 16
        gemm_kernel<128, 64, 2, false><<<(n + NPB - 1) / NPB, 128>>>(x, W1, nullptr, sup, n);
    }
    fill_kernel<64><<<(n * 64 + 255) / 256, 256>>>(abuf, b1, n * 64);
    scatter_kernel<64><<<scat_blocks, 256>>>(sup, src, dst, ew, abuf, E);
    sigmoid_kernel<<<(n * 64 + 255) / 256, 256>>>(abuf, n * 64);

    // ---- Layer 2: a2 = agg(h1) ; feat = sigmoid(a2 @ W2 + b2) ----
    // (aggregate BEFORE the GEMM: 64 feats/edge instead of 128 — linearity)
    fill_kernel<64><<<(n * 64 + 255) / 256, 256>>>(sup, nullptr, n * 64);
    scatter_kernel<64><<<scat_blocks, 256>>>(abuf, src, dst, ew, sup, E);
    {
        constexpr int NPB = (128 / (128 / 4)) * 2;  // 8
        gemm_kernel<64, 128, 2, true><<<(n + NPB - 1) / NPB, 128>>>(sup, W2, b2, feat, n);
    }

    // ---- Layer 3: sup3 = feat @ W3 ; out = b3 + agg(sup3) ----
    {
        constexpr int NPB = (128 / (32 / 4)) * 1;  // 16
        gemm_kernel<128, 32, 1, false><<<(n + NPB - 1) / NPB, 128>>>(feat, W3, nullptr, abuf, n);
    }
    fill_kernel<32><<<(n * 32 + 255) / 256, 256>>>(out, b3, n * 32);
    scatter_kernel<32><<<scat_blocks, 256>>>(abuf, src, dst, ew, out, E);
}

// round 2
// speedup vs baseline: 1.8885x; 1.8885x over previous
#include <cuda_runtime.h>
#include <cuda_bf16.h>

#define MAXN 50000
#define MAXE 500000

// Scratch (__device__ globals: allowed, no allocation)
__device__ float g_sup[MAXN * 64];
__device__ float g_a[MAXN * 64];
__device__ int   g_deg[MAXN];
__device__ int   g_rowptr[MAXN + 1];
__device__ int   g_cur[MAXN];
__device__ int2  g_edges[MAXE];     // {src, bitcast(weight)} grouped by dst
__device__ int   g_bsum[256];
__device__ int   g_boff[256];

// ---------------------------------------------------------------------------
// CSC construction
// ---------------------------------------------------------------------------
__global__ void zero_deg_kernel(int* __restrict__ deg, int n) {
    int i = blockIdx.x * blockDim.x + threadIdx.x;
    if (i < n) deg[i] = 0;
}

__global__ void hist_kernel(const int* __restrict__ dst, int* __restrict__ deg, int E) {
    int e = blockIdx.x * blockDim.x + threadIdx.x;
    if (e < E) atomicAdd(&deg[__ldg(&dst[e])], 1);
}

// Per-block partial sums of deg (256 elems/block)
__global__ void scanA_kernel(const int* __restrict__ deg, int* __restrict__ bsum, int n) {
    __shared__ int s[256];
    int i = blockIdx.x * 256 + threadIdx.x;
    int v = (i < n) ? deg[i] : 0;
    s[threadIdx.x] = v;
    __syncthreads();
    for (int off = 128; off > 0; off >>= 1) {
        if (threadIdx.x < off) s[threadIdx.x] += s[threadIdx.x + off];
        __syncthreads();
    }
    if (threadIdx.x == 0) bsum[blockIdx.x] = s[0];
}

// Exclusive scan of block sums (single block, nblk <= 256)
__global__ void scanB_kernel(const int* __restrict__ bsum, int* __restrict__ boff, int nblk) {
    __shared__ int s[256];
    int t = threadIdx.x;
    s[t] = (t < nblk) ? bsum[t] : 0;
    __syncthreads();
    for (int off = 1; off < 256; off <<= 1) {
        int x = (t >= off) ? s[t - off] : 0;
        __syncthreads();
        s[t] += x;
        __syncthreads();
    }
    if (t < nblk) boff[t] = s[t] - bsum[t];  // exclusive
}

// Per-chunk exclusive scan + offset -> row_ptr (and cursor copy)
__global__ void scanC_kernel(const int* __restrict__ deg, const int* __restrict__ boff,
                             int* __restrict__ rowptr, int* __restrict__ cur, int n, int E) {
    __shared__ int s[256];
    int t = threadIdx.x;
    int i = blockIdx.x * 256 + t;
    int v = (i < n) ? deg[i] : 0;
    s[t] = v;
    __syncthreads();
    for (int off = 1; off < 256; off <<= 1) {
        int x = (t >= off) ? s[t - off] : 0;
        __syncthreads();
        s[t] += x;
        __syncthreads();
    }
    if (i < n) {
        int excl = boff[blockIdx.x] + s[t] - v;
        rowptr[i] = excl;
        cur[i] = excl;
        if (i == n - 1) rowptr[n] = E;
    }
}

__global__ void fill_edges_kernel(const int* __restrict__ src, const int* __restrict__ dst,
                                  const float* __restrict__ ew, int* __restrict__ cur,
                                  int2* __restrict__ edges, int E) {
    int e = blockIdx.x * blockDim.x + threadIdx.x;
    if (e >= E) return;
    int d = __ldg(&dst[e]);
    int pos = atomicAdd(&cur[d], 1);
    edges[pos] = make_int2(__ldg(&src[e]), __float_as_int(__ldg(&ew[e])));
}

// ---------------------------------------------------------------------------
// Pull aggregation: out[d] = (bias?) + sum_{e in in(d)} sup[src_e] * w_e
// One warp per node. M=64 -> float2/lane, M=32 -> float/lane.
// ---------------------------------------------------------------------------
template <int M, bool SIG, bool HASB>
__global__ __launch_bounds__(256) void pull_kernel(
    const float* __restrict__ sup, const int2* __restrict__ edges,
    const int* __restrict__ rowptr, const float* __restrict__ bias,
    float* __restrict__ out, int n) {
    int warp = (blockIdx.x * blockDim.x + threadIdx.x) >> 5;
    int lane = threadIdx.x & 31;
    if (warp >= n) return;
    int beg = __ldg(&rowptr[warp]);
    int end = __ldg(&rowptr[warp + 1]);

    if (M == 64) {
        float2 acc = HASB ? *reinterpret_cast<const float2*>(&bias[lane * 2])
                          : make_float2(0.f, 0.f);
        int e = beg;
        for (; e + 1 < end; e += 2) {
            int2 r0 = __ldg(&edges[e]);
            int2 r1 = __ldg(&edges[e + 1]);
            float2 v0 = *reinterpret_cast<const float2*>(&sup[(size_t)r0.x * 64 + lane * 2]);
            float2 v1 = *reinterpret_cast<const float2*>(&sup[(size_t)r1.x * 64 + lane * 2]);
            float w0 = __int_as_float(r0.y), w1 = __int_as_float(r1.y);
            acc.x += v0.x * w0; acc.y += v0.y * w0;
            acc.x += v1.x * w1; acc.y += v1.y * w1;
        }
        if (e < end) {
            int2 r0 = __ldg(&edges[e]);
            float2 v0 = *reinterpret_cast<const float2*>(&sup[(size_t)r0.x * 64 + lane * 2]);
            float w0 = __int_as_float(r0.y);
            acc.x += v0.x * w0; acc.y += v0.y * w0;
        }
        if (SIG) {
            acc.x = 1.0f / (1.0f + __expf(-acc.x));
            acc.y = 1.0f / (1.0f + __expf(-acc.y));
        }
        *reinterpret_cast<float2*>(&out[(size_t)warp * 64 + lane * 2]) = acc;
    } else {  // M == 32
        float acc = HASB ? __ldg(&bias[lane]) : 0.f;
        int e = beg;
        for (; e + 1 < end; e += 2) {
            int2 r0 = __ldg(&edges[e]);
            int2 r1 = __ldg(&edges[e + 1]);
            float v0 = __ldg(&sup[(size_t)r0.x * 32 + lane]);
            float v1 = __ldg(&sup[(size_t)r1.x * 32 + lane]);
            acc += v0 * __int_as_float(r0.y);
            acc += v1 * __int_as_float(r1.y);
        }
        if (e < end) {
            int2 r0 = __ldg(&edges[e]);
            acc += __ldg(&sup[(size_t)r0.x * 32 + lane]) * __int_as_float(r0.y);
        }
        if (SIG) acc = 1.0f / (1.0f + __expf(-acc));
        out[(size_t)warp * 32 + lane] = acc;
    }
}

// ---------------------------------------------------------------------------
// GEMM: out[n,M] = H[n,K] @ W[K,M] (+bias, +sigmoid). K chunked to fit smem.
// ---------------------------------------------------------------------------
template <int K, int M, int TN, int KC, bool SIG>
__global__ __launch_bounds__(128) void gemm_kernel(
    const float* __restrict__ H, const float* __restrict__ Wm,
    const float* __restrict__ bias, float* __restrict__ out, int n) {
    constexpr int THREADS = 128;
    constexpr int TM = 4;
    constexpr int FG = M / TM;
    constexpr int NPB = (THREADS / FG) * TN;

    __shared__ float shW[K * M];
    __shared__ float shX[NPB][KC + 1];

    int node0 = blockIdx.x * NPB;
    for (int i = threadIdx.x; i < K * M; i += THREADS) shW[i] = Wm[i];

    int group = threadIdx.x / FG;
    int f0 = (threadIdx.x % FG) * TM;

    float acc[TN][TM];
#pragma unroll
    for (int t = 0; t < TN; t++)
#pragma unroll
        for (int j = 0; j < TM; j++) acc[t][j] = 0.0f;

    for (int k0 = 0; k0 < K; k0 += KC) {
        __syncthreads();
        for (int i = threadIdx.x; i < NPB * KC; i += THREADS) {
            int r = i / KC, c = i - r * KC;
            int node = node0 + r;
            shX[r][c] = (node < n) ? H[(size_t)node * K + k0 + c] : 0.0f;
        }
        __syncthreads();
#pragma unroll
        for (int k = 0; k < KC; k++) {
            float4 wv = *reinterpret_cast<const float4*>(&shW[(k0 + k) * M + f0]);
#pragma unroll
            for (int t = 0; t < TN; t++) {
                float xv = shX[group * TN + t][k];
                acc[t][0] += xv * wv.x;
                acc[t][1] += xv * wv.y;
                acc[t][2] += xv * wv.z;
                acc[t][3] += xv * wv.w;
            }
        }
    }

#pragma unroll
    for (int t = 0; t < TN; t++) {
        int node = node0 + group * TN + t;
        if (node >= n) continue;
        float4 r;
        if (SIG) {
            float4 bv = *reinterpret_cast<const float4*>(&bias[f0]);
            r.x = 1.0f / (1.0f + __expf(-(acc[t][0] + bv.x)));
            r.y = 1.0f / (1.0f + __expf(-(acc[t][1] + bv.y)));
            r.z = 1.0f / (1.0f + __expf(-(acc[t][2] + bv.z)));
            r.w = 1.0f / (1.0f + __expf(-(acc[t][3] + bv.w)));
        } else {
            r.x = acc[t][0]; r.y = acc[t][1]; r.z = acc[t][2]; r.w = acc[t][3];
        }
        *reinterpret_cast<float4*>(&out[(size_t)node * M + f0]) = r;
    }
}

extern "C" void kernel_launch(void* const* d_in, const int* in_sizes, int n_in,
                              void* d_out, int out_size) {
    const float* x  = (const float*)d_in[0];
    const int*   ei = (const int*)d_in[1];
    const float* ew = (const float*)d_in[2];
    const float* W1 = (const float*)d_in[3];
    const float* b1 = (const float*)d_in[4];
    const float* W2 = (const float*)d_in[5];
    const float* b2 = (const float*)d_in[6];
    const float* W3 = (const float*)d_in[7];
    const float* b3 = (const float*)d_in[8];

    int n = in_sizes[0] / 128;   // 50000
    int E = in_sizes[2];         // 500000
    const int* src = ei;
    const int* dst = ei + E;

    float* out  = (float*)d_out;             // [n, 32]
    float* feat = out + (size_t)n * 32;      // [n, 128]

    float *sup, *abuf;
    int *deg, *rowptr, *cur, *boffp, *bsump;
    int2* edges;
    cudaGetSymbolAddress((void**)&sup, g_sup);
    cudaGetSymbolAddress((void**)&abuf, g_a);
    cudaGetSymbolAddress((void**)&deg, g_deg);
    cudaGetSymbolAddress((void**)&rowptr, g_rowptr);
    cudaGetSymbolAddress((void**)&cur, g_cur);
    cudaGetSymbolAddress((void**)&edges, g_edges);
    cudaGetSymbolAddress((void**)&bsump, g_bsum);
    cudaGetSymbolAddress((void**)&boffp, g_boff);

    int nblk = (n + 255) / 256;  // 196 <= 256

    // ---- CSC build (once, reused by all 3 aggregations) ----
    zero_deg_kernel<<<nblk, 256>>>(deg, n);
    hist_kernel<<<(E + 255) / 256, 256>>>(dst, deg, E);
    scanA_kernel<<<nblk, 256>>>(deg, bsump, n);
    scanB_kernel<<<1, 256>>>(bsump, boffp, nblk);
    scanC_kernel<<<nblk, 256>>>(deg, boffp, rowptr, cur, n, E);
    fill_edges_kernel<<<(E + 255) / 256, 256>>>(src, dst, ew, cur, edges, E);

    int pull_grid = (n + 7) / 8;  // 8 warps/block

    // ---- Layer 1: sup = x@W1 ; h1 = sigmoid(agg(sup) + b1) -> abuf ----
    gemm_kernel<128, 64, 4, 64, false><<<(n + 31) / 32, 128>>>(x, W1, nullptr, sup, n);
    pull_kernel<64, true, true><<<pull_grid, 256>>>(sup, edges, rowptr, b1, abuf, n);

    // ---- Layer 2: a2 = agg(h1) -> sup ; feat = sigmoid(a2@W2 + b2) ----
    pull_kernel<64, false, false><<<pull_grid, 256>>>(abuf, edges, rowptr, nullptr, sup, n);
    gemm_kernel<64, 128, 8, 64, true><<<(n + 31) / 32, 128>>>(sup, W2, b2, feat, n);

    // ---- Layer 3: sup3 = feat@W3 -> abuf ; out = agg(sup3) + b3 ----
    gemm_kernel<128, 32, 4, 64, false><<<(n + 63) / 64, 128>>>(feat, W3, nullptr, abuf, n);
    pull_kernel<32, false, true><<<pull_grid, 256>>>(abuf, edges, rowptr, b3, out, n);
}

// round 3
// speedup vs baseline: 2.2174x; 1.1742x over previous
#include <cuda_runtime.h>
#include <cuda_bf16.h>
#include <cstdint>

#define MAXN 50000
#define MAXE 500000

// Scratch (__device__ globals: allowed, no allocation)
__device__ float g_sup[MAXN * 64];
__device__ float g_a[MAXN * 64];
__device__ int   g_deg[MAXN];
__device__ int   g_start[MAXN];
__device__ int   g_cur[MAXN];
__device__ int   g_counter;
__device__ int2  g_edges[MAXE];   // {src, bitcast(weight)} grouped by dst

// ---------------------------------------------------------------------------
// CSC construction (scan-free: atomic segment allocation, order irrelevant)
// ---------------------------------------------------------------------------
__global__ void zero_deg_kernel(int* __restrict__ deg, int* __restrict__ counter, int n) {
    int i = blockIdx.x * blockDim.x + threadIdx.x;
    if (i < n) deg[i] = 0;
    if (i == 0) *counter = 0;
}

__global__ void hist_kernel(const int* __restrict__ dst, int* __restrict__ deg, int E) {
    int e = blockIdx.x * blockDim.x + threadIdx.x;
    if (e < E) atomicAdd(&deg[__ldg(&dst[e])], 1);
}

__global__ void assign_kernel(const int* __restrict__ deg, int* __restrict__ counter,
                              int* __restrict__ start, int* __restrict__ cur, int n) {
    int i = blockIdx.x * blockDim.x + threadIdx.x;
    if (i < n) {
        int s = atomicAdd(counter, deg[i]);
        start[i] = s;
        cur[i] = s;
    }
}

__global__ void fill_edges_kernel(const int* __restrict__ src, const int* __restrict__ dst,
                                  const float* __restrict__ ew, int* __restrict__ cur,
                                  int2* __restrict__ edges, int E) {
    int e = blockIdx.x * blockDim.x + threadIdx.x;
    if (e >= E) return;
    int d = __ldg(&dst[e]);
    int pos = atomicAdd(&cur[d], 1);
    edges[pos] = make_int2(__ldg(&src[e]), __float_as_int(__ldg(&ew[e])));
}

// ---------------------------------------------------------------------------
// Pull aggregation: out[d] = (bias?) + sum_{e in in(d)} sup[src_e] * w_e
// One warp per node. M=64 -> float2/lane, M=32 -> float/lane.
// ---------------------------------------------------------------------------
template <int M, bool SIG, bool HASB>
__global__ __launch_bounds__(256) void pull_kernel(
    const float* __restrict__ sup, const int2* __restrict__ edges,
    const int* __restrict__ start, const int* __restrict__ deg,
    const float* __restrict__ bias, float* __restrict__ out, int n) {
    int warp = (blockIdx.x * blockDim.x + threadIdx.x) >> 5;
    int lane = threadIdx.x & 31;
    if (warp >= n) return;
    int beg = __ldg(&start[warp]);
    int end = beg + __ldg(&deg[warp]);

    if (M == 64) {
        float2 acc = HASB ? *reinterpret_cast<const float2*>(&bias[lane * 2])
                          : make_float2(0.f, 0.f);
        int e = beg;
        for (; e + 1 < end; e += 2) {
            int2 r0 = __ldg(&edges[e]);
            int2 r1 = __ldg(&edges[e + 1]);
            float2 v0 = *reinterpret_cast<const float2*>(&sup[(size_t)r0.x * 64 + lane * 2]);
            float2 v1 = *reinterpret_cast<const float2*>(&sup[(size_t)r1.x * 64 + lane * 2]);
            float w0 = __int_as_float(r0.y), w1 = __int_as_float(r1.y);
            acc.x += v0.x * w0; acc.y += v0.y * w0;
            acc.x += v1.x * w1; acc.y += v1.y * w1;
        }
        if (e < end) {
            int2 r0 = __ldg(&edges[e]);
            float2 v0 = *reinterpret_cast<const float2*>(&sup[(size_t)r0.x * 64 + lane * 2]);
            float w0 = __int_as_float(r0.y);
            acc.x += v0.x * w0; acc.y += v0.y * w0;
        }
        if (SIG) {
            acc.x = 1.0f / (1.0f + __expf(-acc.x));
            acc.y = 1.0f / (1.0f + __expf(-acc.y));
        }
        *reinterpret_cast<float2*>(&out[(size_t)warp * 64 + lane * 2]) = acc;
    } else {  // M == 32
        float acc = HASB ? __ldg(&bias[lane]) : 0.f;
        int e = beg;
        for (; e + 1 < end; e += 2) {
            int2 r0 = __ldg(&edges[e]);
            int2 r1 = __ldg(&edges[e + 1]);
            float v0 = __ldg(&sup[(size_t)r0.x * 32 + lane]);
            float v1 = __ldg(&sup[(size_t)r1.x * 32 + lane]);
            acc += v0 * __int_as_float(r0.y);
            acc += v1 * __int_as_float(r1.y);
        }
        if (e < end) {
            int2 r0 = __ldg(&edges[e]);
            acc += __ldg(&sup[(size_t)r0.x * 32 + lane]) * __int_as_float(r0.y);
        }
        if (SIG) acc = 1.0f / (1.0f + __expf(-acc));
        out[(size_t)warp * 32 + lane] = acc;
    }
}

// ---------------------------------------------------------------------------
// bf16-split tensor-core GEMM: out[n,M] = H[n,K] @ W[K,M] (+bias +sigmoid)
// fp32 -> hi/lo bf16 split; D = Ahi*Bhi + Ahi*Blo + Alo*Bhi  (err ~8e-6)
// Block: 128 threads (4 warps), 64 nodes/block, full W in smem.
// ---------------------------------------------------------------------------
__device__ __forceinline__ void split2(float x, float y, uint32_t& hi, uint32_t& lo) {
    __nv_bfloat16 hx = __float2bfloat16(x);
    __nv_bfloat16 hy = __float2bfloat16(y);
    __nv_bfloat16 lx = __float2bfloat16(x - __bfloat162float(hx));
    __nv_bfloat16 ly = __float2bfloat16(y - __bfloat162float(hy));
    hi = (uint32_t)__bfloat16_as_ushort(hx) | ((uint32_t)__bfloat16_as_ushort(hy) << 16);
    lo = (uint32_t)__bfloat16_as_ushort(lx) | ((uint32_t)__bfloat16_as_ushort(ly) << 16);
}

__device__ __forceinline__ void mma_bf16(float* c, const uint32_t* a, uint32_t b0, uint32_t b1) {
    asm volatile(
        "mma.sync.aligned.m16n8k16.row.col.f32.bf16.bf16.f32 "
        "{%0,%1,%2,%3}, {%4,%5,%6,%7}, {%8,%9}, {%0,%1,%2,%3};\n"
        : "+f"(c[0]), "+f"(c[1]), "+f"(c[2]), "+f"(c[3])
        : "r"(a[0]), "r"(a[1]), "r"(a[2]), "r"(a[3]), "r"(b0), "r"(b1));
}

template <int K, int M, bool SIG>
__global__ __launch_bounds__(128) void mma_gemm_kernel(
    const float* __restrict__ H, const float* __restrict__ Wm,
    const float* __restrict__ bias, float* __restrict__ out, int n) {
    constexpr int KP = K / 2;       // packed k-pairs
    constexpr int MS = M + 8;       // stride ≡ 8 (mod 32): conflict-free B frags
    constexpr int NJ = M / 8;       // n-steps

    __shared__ uint32_t shWhi[KP * MS];
    __shared__ uint32_t shWlo[KP * MS];
    __shared__ float shA[64][17];

    int tid = threadIdx.x;
    int warp = tid >> 5, lane = tid & 31;
    int g = lane >> 2, t = lane & 3;
    int node0 = blockIdx.x * 64;

    // Load W, split into hi/lo bf16 pairs: shW[kp*MS + m] packs (k=2kp, k=2kp+1)
    for (int i = tid; i < KP * M; i += 128) {
        int kp = i / M, m = i - kp * M;
        split2(Wm[(2 * kp) * M + m], Wm[(2 * kp + 1) * M + m],
               shWhi[kp * MS + m], shWlo[kp * MS + m]);
    }

    float acc[NJ][4];
#pragma unroll
    for (int j = 0; j < NJ; j++)
#pragma unroll
        for (int q = 0; q < 4; q++) acc[j][q] = 0.0f;

    int rb = warp * 16;

    for (int k0 = 0; k0 < K; k0 += 16) {
        __syncthreads();
        for (int i = tid; i < 64 * 16; i += 128) {
            int r = i >> 4, c = i & 15;
            int node = node0 + r;
            shA[r][c] = (node < n) ? H[(size_t)node * K + k0 + c] : 0.0f;
        }
        __syncthreads();

        // A fragments (m16n8k16 row-major): rows rb+g, rb+g+8; cols t*2(+1), +8
        uint32_t ahi[4], alo[4];
        int r0 = rb + g;
        split2(shA[r0][t * 2],     shA[r0][t * 2 + 1],     ahi[0], alo[0]);
        split2(shA[r0 + 8][t * 2], shA[r0 + 8][t * 2 + 1], ahi[1], alo[1]);
        split2(shA[r0][t * 2 + 8],     shA[r0][t * 2 + 9],     ahi[2], alo[2]);
        split2(shA[r0 + 8][t * 2 + 8], shA[r0 + 8][t * 2 + 9], ahi[3], alo[3]);

        int kp0 = k0 >> 1;
#pragma unroll
        for (int j = 0; j < NJ; j++) {
            int nn = j * 8 + g;
            uint32_t bh0 = shWhi[(kp0 + t) * MS + nn];
            uint32_t bh1 = shWhi[(kp0 + t + 4) * MS + nn];
            uint32_t bl0 = shWlo[(kp0 + t) * MS + nn];
            uint32_t bl1 = shWlo[(kp0 + t + 4) * MS + nn];
            mma_bf16(acc[j], ahi, bh0, bh1);
            mma_bf16(acc[j], ahi, bl0, bl1);
            mma_bf16(acc[j], alo, bh0, bh1);
        }
    }

    // Epilogue: c0,c1 at (rb+g, n0,n0+1); c2,c3 at (rb+g+8, n0,n0+1)
    int node_a = node0 + rb + g;
    int node_b = node_a + 8;
#pragma unroll
    for (int j = 0; j < NJ; j++) {
        int n0 = j * 8 + t * 2;
        float v0 = acc[j][0], v1 = acc[j][1], v2 = acc[j][2], v3 = acc[j][3];
        if (SIG) {
            float2 bv = *reinterpret_cast<const float2*>(&bias[n0]);
            v0 = 1.0f / (1.0f + __expf(-(v0 + bv.x)));
            v1 = 1.0f / (1.0f + __expf(-(v1 + bv.y)));
            v2 = 1.0f / (1.0f + __expf(-(v2 + bv.x)));
            v3 = 1.0f / (1.0f + __expf(-(v3 + bv.y)));
        }
        if (node_a < n)
            *reinterpret_cast<float2*>(&out[(size_t)node_a * M + n0]) = make_float2(v0, v1);
        if (node_b < n)
            *reinterpret_cast<float2*>(&out[(size_t)node_b * M + n0]) = make_float2(v2, v3);
    }
}

extern "C" void kernel_launch(void* const* d_in, const int* in_sizes, int n_in,
                              void* d_out, int out_size) {
    const float* x  = (const float*)d_in[0];
    const int*   ei = (const int*)d_in[1];
    const float* ew = (const float*)d_in[2];
    const float* W1 = (const float*)d_in[3];
    const float* b1 = (const float*)d_in[4];
    const float* W2 = (const float*)d_in[5];
    const float* b2 = (const float*)d_in[6];
    const float* W3 = (const float*)d_in[7];
    const float* b3 = (const float*)d_in[8];

    int n = in_sizes[0] / 128;   // 50000
    int E = in_sizes[2];         // 500000
    const int* src = ei;
    const int* dst = ei + E;

    float* out  = (float*)d_out;             // [n, 32]
    float* feat = out + (size_t)n * 32;      // [n, 128]

    float *sup, *abuf;
    int *deg, *startp, *cur, *counter;
    int2* edges;
    cudaGetSymbolAddress((void**)&sup, g_sup);
    cudaGetSymbolAddress((void**)&abuf, g_a);
    cudaGetSymbolAddress((void**)&deg, g_deg);
    cudaGetSymbolAddress((void**)&startp, g_start);
    cudaGetSymbolAddress((void**)&cur, g_cur);
    cudaGetSymbolAddress((void**)&counter, g_counter);
    cudaGetSymbolAddress((void**)&edges, g_edges);

    int nblk = (n + 255) / 256;

    // ---- CSC build (scan-free) ----
    zero_deg_kernel<<<nblk, 256>>>(deg, counter, n);
    hist_kernel<<<(E + 255) / 256, 256>>>(dst, deg, E);
    assign_kernel<<<nblk, 256>>>(deg, counter, startp, cur, n);
    fill_edges_kernel<<<(E + 255) / 256, 256>>>(src, dst, ew, cur, edges, E);

    int pull_grid = (n + 7) / 8;     // 8 warps/block
    int gemm_grid = (n + 63) / 64;

    // ---- Layer 1: sup = x@W1 ; h1 = sigmoid(agg(sup) + b1) -> abuf ----
    mma_gemm_kernel<128, 64, false><<<gemm_grid, 128>>>(x, W1, nullptr, sup, n);
    pull_kernel<64, true, true><<<pull_grid, 256>>>(sup, edges, startp, deg, b1, abuf, n);

    // ---- Layer 2: a2 = agg(h1) -> sup ; feat = sigmoid(a2@W2 + b2) ----
    pull_kernel<64, false, false><<<pull_grid, 256>>>(abuf, edges, startp, deg, nullptr, sup, n);
    mma_gemm_kernel<64, 128, true><<<gemm_grid, 128>>>(sup, W2, b2, feat, n);

    // ---- Layer 3: sup3 = feat@W3 -> abuf ; out = agg(sup3) + b3 ----
    mma_gemm_kernel<128, 32, false><<<gemm_grid, 128>>>(feat, W3, nullptr, abuf, n);
    pull_kernel<32, false, true><<<pull_grid, 256>>>(abuf, edges, startp, deg, b3, out, n);
}